// round 6
// baseline (speedup 1.0000x reference)
#include <cuda_runtime.h>
#include <stdint.h>

// PatchShift: out[b,t,h,w,c] = x[b, (t - S[h%3, w%3]) % 8, h, w, c]
// Shapes: B=32, T=8, H=14, W=14, C=768 (fp32) -> rows of 192 float4.
// Persistent-style: 1480 CTAs (148 SM x 10), grid-stride over 6272 (b,hw)
// units. Each unit: 8 front-batched float4 loads (one per source t-slice)
// then 8 stores. Plain cache policy (R3/R4 showed hints regress). Stores are
// fire-and-forget so successive units pipeline back-to-back; no wave
// transitions, prologue amortized ~4x.

#define B_ 32
#define T_ 8
#define H_ 14
#define W_ 14
#define C4_ 192                         // 768 floats = 192 float4
#define HW_ (H_ * W_)                   // 196
#define NUNITS (B_ * HW_)               // 6272
#define TSTRIDE (HW_ * C4_)             // float4 stride between time slices = 37632
#define NCTA 1480                       // 148 SMs x 10 CTAs (6 warps each)

__global__ __launch_bounds__(C4_) void patch_shift_kernel(
    const float4* __restrict__ x, float4* __restrict__ out)
{
    const int tid = threadIdx.x;

    for (int u = blockIdx.x; u < NUNITS; u += NCTA) {
        const int b  = u / HW_;          // constant divisor -> mulhi
        const int hw = u - b * HW_;      // 0..195
        const int w  = hw % 14;
        const int h  = hw / 14;

        const int Stab[9] = {-4, 1, 2, -1, 0, 3, -2, -3, 4};
        const int s = Stab[(h % 3) * 3 + (w % 3)];

        // base index of (b, t=0, h, w, c4=tid); fits in 32 bits (max ~9.6M)
        const int base = (b * (T_ * HW_) + hw) * C4_ + tid;

        float4 v[T_];
        #pragma unroll
        for (int t = 0; t < T_; ++t) {
            const int ts = (t - s + 8) & 7;      // source time slice
            v[t] = x[base + ts * TSTRIDE];
        }
        #pragma unroll
        for (int t = 0; t < T_; ++t) {
            out[base + t * TSTRIDE] = v[t];
        }
    }
}

extern "C" void kernel_launch(void* const* d_in, const int* in_sizes, int n_in,
                              void* d_out, int out_size)
{
    const float4* x   = (const float4*)d_in[0];
    float4*       out = (float4*)d_out;

    patch_shift_kernel<<<NCTA, C4_>>>(x, out);
}

// round 7
// speedup vs baseline: 1.1076x; 1.1076x over previous
#include <cuda_runtime.h>
#include <stdint.h>

// PatchShift: out[b,t,h,w,c] = x[b, (t - S[h%3, w%3]) % 8, h, w, c]
// Shapes: B=32, T=8, H=14, W=14, C=768 (fp32) -> 37632 float4 per (b,t) slice.
// Flattened spatial mapping: thread owns flat i = hw*192 + c4 inside one batch
// slice and copies that float4 across all T=8 slices (8 front-batched loads,
// 8 stores). 256-thread CTAs tile the 2048-thread/SM cap exactly (8 CTAs/SM
// = 64 warps, 100% occupancy) — R2's 192-thr blocks capped at 60/64.
// Plain cache policy (hints regressed in R3/R4); hardware-scheduled CTAs
// (persistent loop regressed in R6).

#define B_ 32
#define T_ 8
#define HW_ 196                          // 14*14
#define C4_ 192                          // 768 floats = 192 float4
#define SLICE (HW_ * C4_)                // 37632 float4 per (b,t) slice
#define NTHR 256

__global__ __launch_bounds__(NTHR) void patch_shift_kernel(
    const float4* __restrict__ x, float4* __restrict__ out)
{
    // blockIdx.x in [0,147): covers SLICE/NTHR chunks; blockIdx.y = b
    const int i  = blockIdx.x * NTHR + threadIdx.x;  // 0..37631, flat (hw,c4)
    const int b  = blockIdx.y;

    const int hw = i / C4_;              // constant divisor -> mulhi
    const int w  = hw % 14;
    const int h  = hw / 14;

    const int Stab[9] = {-4, 1, 2, -1, 0, 3, -2, -3, 4};
    const int s = Stab[(h % 3) * 3 + (w % 3)];

    // base index of (b, t=0, flat i); total tensor 9.63M float4 < 2^31
    const int base = b * (T_ * SLICE) + i;

    float4 v[T_];
    #pragma unroll
    for (int t = 0; t < T_; ++t) {
        const int ts = (t - s + 8) & 7;          // source time slice
        v[t] = x[base + ts * SLICE];
    }
    #pragma unroll
    for (int t = 0; t < T_; ++t) {
        out[base + t * SLICE] = v[t];
    }
}

extern "C" void kernel_launch(void* const* d_in, const int* in_sizes, int n_in,
                              void* d_out, int out_size)
{
    const float4* x   = (const float4*)d_in[0];
    float4*       out = (float4*)d_out;

    dim3 grid(SLICE / NTHR, B_);         // (147, 32) = 4704 CTAs, 256 thr each
    patch_shift_kernel<<<grid, NTHR>>>(x, out);
}

// round 8
// speedup vs baseline: 1.1154x; 1.0071x over previous
#include <cuda_runtime.h>
#include <stdint.h>

// PatchShift: out[b,t,h,w,c] = x[b, (t - S[h%3, w%3]) % 8, h, w, c]
// Shapes: B=32, T=8, H=14, W=14, C=768 (fp32) -> rows of 192 float4.
// FINAL (= Round-2 winner, best of 7 measured variants at 41.5us kernel,
// DRAM 77.2%, effective 7.4 TB/s incl. L2 hits ~ LTS chip cap):
// One CTA per (b,h,w); each thread copies its channel float4 across all T=8
// slices with 8 front-batched independent loads (MLP=8), then 8 stores.
// Default cache policy (evict-first and L1-bypass hints both regressed);
// 64-bit index math (ptxas' own pipeline scheduling at regs=30 beat manual
// 32-bit variants); hardware CTA scheduling (persistent loop regressed).

#define B_ 32
#define T_ 8
#define H_ 14
#define W_ 14
#define C4_ 192                         // 768 floats = 192 float4
#define TSTRIDE (H_ * W_ * C4_)         // float4 stride between time slices = 37632

__global__ __launch_bounds__(C4_) void patch_shift_kernel(
    const float4* __restrict__ x, float4* __restrict__ out)
{
    // blockIdx.x = h*14 + w (0..195), blockIdx.y = b (0..31)
    const int hw = blockIdx.x;
    const int w  = hw % 14;             // constant divisor -> mul/shift
    const int h  = hw / 14;
    const int b  = blockIdx.y;

    const int Stab[9] = {-4, 1, 2, -1, 0, 3, -2, -3, 4};
    const int s = Stab[(h % 3) * 3 + (w % 3)];

    // base index of (b, t=0, h, w, c4=tid)
    const long long base = ((long long)b * T_ * H_ * W_ + hw) * C4_ + threadIdx.x;

    float4 v[T_];
    #pragma unroll
    for (int t = 0; t < T_; ++t) {
        const int ts = (t - s + 8) & 7;          // source time slice
        v[t] = x[base + (long long)ts * TSTRIDE];
    }
    #pragma unroll
    for (int t = 0; t < T_; ++t) {
        out[base + (long long)t * TSTRIDE] = v[t];
    }
}

extern "C" void kernel_launch(void* const* d_in, const int* in_sizes, int n_in,
                              void* d_out, int out_size)
{
    const float4* x   = (const float4*)d_in[0];
    float4*       out = (float4*)d_out;

    dim3 grid(H_ * W_, B_);             // (196, 32) = 6272 CTAs
    patch_shift_kernel<<<grid, C4_>>>(x, out);
}